// round 16
// baseline (speedup 1.0000x reference)
#include <cuda_runtime.h>
#include <cstdint>

// Word2DM, fused persistent kernel, software-pipelined Phase A (cp.async depth 3):
// Phase 0 : epoch-stamped mark + warp-aggregated dense-list append (no scan).
// Phase A : per-warp HMMA Gram over dense list; 3-deep cp.async pipeline hides DRAM.
// Phase B : per-sample target Gram + 11 batched triangle dots, product-form softplus;
//           last-arriving block does the fixed-order mean.
// Launch identity via serialized ticket counter (race-free, replay-safe).

#define NDIM      20
#define NMATS     11
#define BMAX      32768
#define VOCAB_MAX 100000
#define TPAIRS    110
#define TSTRIDE   112
#define DEPTH     3

__device__ float    g_partials[BMAX];
__device__ uint32_t g_hfeat[(size_t)VOCAB_MAX * TSTRIDE];   // 44.8 MB
__device__ unsigned g_flagse[VOCAB_MAX];                    // epoch stamps
__device__ int      g_list[VOCAB_MAX];
__device__ unsigned g_cnt2[2];     // parity ping-pong append counters
__device__ unsigned g_launch;      // launch ticket counter (monotonic)
__device__ unsigned g_bar;         // grid-barrier epochs (monotonic)
__device__ unsigned g_ctr;         // last-block-reduce counter (modulo pattern)

typedef unsigned long long ull;

static __device__ __forceinline__ uint32_t hfma2(uint32_t a, uint32_t b, uint32_t c) {
    uint32_t d;
    asm("fma.rn.bf16x2 %0, %1, %2, %3;" : "=r"(d) : "r"(a), "r"(b), "r"(c));
    return d;
}
static __device__ __forceinline__ uint32_t hadd2(uint32_t a, uint32_t b) {
    uint32_t d;
    asm("add.bf16x2 %0, %1, %2;" : "=r"(d) : "r"(a), "r"(b));
    return d;
}
static __device__ __forceinline__ uint32_t hmul2(uint32_t a, uint32_t b) {
    uint32_t d;
    asm("mul.bf16x2 %0, %1, %2;" : "=r"(d) : "r"(a), "r"(b));
    return d;
}
static __device__ __forceinline__ uint32_t prmt(uint32_t a, uint32_t b, uint32_t sel) {
    uint32_t d;
    asm("prmt.b32 %0, %1, %2, %3;" : "=r"(d) : "r"(a), "r"(b), "r"(sel));
    return d;
}
static __device__ __forceinline__ ull packu2(uint32_t lo, uint32_t hi) {
    ull r;
    asm("mov.b64 %0, {%1, %2};" : "=l"(r) : "r"(lo), "r"(hi));
    return r;
}
static __device__ __forceinline__ uint32_t bf2(float hi, float lo) {
    uint32_t r;
    asm("cvt.rn.bf16x2.f32 %0, %1, %2;" : "=r"(r) : "f"(hi), "f"(lo));
    return r;
}
static __device__ __forceinline__ uint32_t smem_u32(const void* p) {
    uint32_t a;
    asm("{ .reg .u64 t; cvta.to.shared.u64 t, %1; cvt.u32.u64 %0, t; }" : "=r"(a) : "l"(p));
    return a;
}
static __device__ __forceinline__ void ldsm_x4(uint32_t& r0, uint32_t& r1,
                                               uint32_t& r2, uint32_t& r3, uint32_t addr) {
    asm volatile("ldmatrix.sync.aligned.m8n8.x4.shared.b16 {%0,%1,%2,%3}, [%4];"
                 : "=r"(r0), "=r"(r1), "=r"(r2), "=r"(r3) : "r"(addr));
}
static __device__ __forceinline__ void mma_bf16(float& d0, float& d1, float& d2, float& d3,
                                                uint32_t a0, uint32_t a1, uint32_t a2, uint32_t a3,
                                                uint32_t b0, uint32_t b1,
                                                float c0, float c1, float c2, float c3) {
    asm volatile("mma.sync.aligned.m16n8k16.row.col.f32.bf16.bf16.f32 "
                 "{%0,%1,%2,%3}, {%4,%5,%6,%7}, {%8,%9}, {%10,%11,%12,%13};"
                 : "=f"(d0), "=f"(d1), "=f"(d2), "=f"(d3)
                 : "r"(a0), "r"(a1), "r"(a2), "r"(a3), "r"(b0), "r"(b1),
                   "f"(c0), "f"(c1), "f"(c2), "f"(c3));
}

static __device__ __forceinline__ void grid_barrier() {
    __syncthreads();
    if (threadIdx.x == 0) {
        __threadfence();
        unsigned o = atomicAdd(&g_bar, 1u);
        unsigned target = (o / gridDim.x + 1u) * gridDim.x;
        while ((int)(*(volatile unsigned*)&g_bar - target) < 0) { }
        __threadfence();
    }
    __syncthreads();
}

static __device__ __forceinline__ int trow(int i) {
    int t = i >> 1;
    return (i & 1) ? (20 * t + 10 - t * t) : (t * (21 - t));
}

static __device__ __forceinline__ void zero_tile(uint16_t* dst16, int lane) {
    uint4 z = make_uint4(0, 0, 0, 0);
    #pragma unroll
    for (int k = 0; k < 4; k++)
        *(uint4*)(dst16 + (lane + 32 * k) * 8) = z;
}

// one word's rows (400 f32 = 100x16B) via cp.async.cg, evict-first L2 policy
static __device__ __forceinline__ void cp_word(uint32_t sdst, const float* __restrict__ src,
                                               int lane, ull pol)
{
    #pragma unroll
    for (int k = 0; k < 4; k++) {
        int f = lane + 32 * k;
        if (f < 100)
            asm volatile("cp.async.cg.shared.global.L2::cache_hint [%0], [%1], 16, %2;"
                         :: "r"(sdst + (uint32_t)f * 16), "l"(src + f * 4), "l"(pol) : "memory");
    }
}
// convert fp32 staging buffer -> bf16 tile (64B row stride; pads untouched)
static __device__ __forceinline__ void conv_word(uint16_t* __restrict__ dst16,
                                                 const float* __restrict__ buf, int lane)
{
    const float4* s = (const float4*)buf;
    #pragma unroll
    for (int k = 0; k < 4; k++) {
        int f = lane + 32 * k;
        if (f < 100) {
            float4 v = s[f];
            int row = f / 5, q = f % 5;
            *(ull*)(dst16 + row * 32 + q * 4) = packu2(bf2(v.y, v.x), bf2(v.w, v.z));
        }
    }
}
static __device__ __forceinline__ void ld_word(float4* v, const float* __restrict__ src, int lane) {
    const float4* s = (const float4*)src;
    #pragma unroll
    for (int k = 0; k < 4; k++) {
        int f = lane + 32 * k;
        if (f < 100) v[k] = __ldcs(s + f);
    }
}
static __device__ __forceinline__ void sts_word(uint16_t* __restrict__ dst16,
                                                const float4* v, int lane) {
    #pragma unroll
    for (int k = 0; k < 4; k++) {
        int f = lane + 32 * k;
        if (f < 100) {
            int row = f / 5, q = f % 5;
            *(ull*)(dst16 + row * 32 + q * 4) =
                packu2(bf2(v[k].y, v[k].x), bf2(v[k].w, v[k].z));
        }
    }
}

__device__ __constant__ const int TILE_M0_[4] = {0, 0, 0, 16};
__device__ __constant__ const int TILE_N0_[4] = {0, 8, 16, 16};

static __device__ __forceinline__ void gram_hmma(uint32_t sb, int lane, float d[4][4]) {
    const int r = lane & 7, g = lane >> 3;
    uint32_t adr = sb + (uint32_t)((r + ((g & 1) ? 8 : 0)) * 64 + ((g >> 1) ? 16 : 0));
    uint32_t X00[4], X01[4], X10[4], X11[4];
    ldsm_x4(X00[0], X00[1], X00[2], X00[3], adr);
    ldsm_x4(X01[0], X01[1], X01[2], X01[3], adr + 32);
    ldsm_x4(X10[0], X10[1], X10[2], X10[3], adr + 1024);
    ldsm_x4(X11[0], X11[1], X11[2], X11[3], adr + 1024 + 32);

    #pragma unroll
    for (int t = 0; t < 4; t++) d[t][0] = d[t][1] = d[t][2] = d[t][3] = 0.0f;

    mma_bf16(d[0][0], d[0][1], d[0][2], d[0][3], X00[0], X00[1], X00[2], X00[3],
             X00[0], X00[2], d[0][0], d[0][1], d[0][2], d[0][3]);
    mma_bf16(d[0][0], d[0][1], d[0][2], d[0][3], X01[0], X01[1], X01[2], X01[3],
             X01[0], X01[2], d[0][0], d[0][1], d[0][2], d[0][3]);
    mma_bf16(d[1][0], d[1][1], d[1][2], d[1][3], X00[0], X00[1], X00[2], X00[3],
             X00[1], X00[3], d[1][0], d[1][1], d[1][2], d[1][3]);
    mma_bf16(d[1][0], d[1][1], d[1][2], d[1][3], X01[0], X01[1], X01[2], X01[3],
             X01[1], X01[3], d[1][0], d[1][1], d[1][2], d[1][3]);
    mma_bf16(d[2][0], d[2][1], d[2][2], d[2][3], X00[0], X00[1], X00[2], X00[3],
             X10[0], X10[2], d[2][0], d[2][1], d[2][2], d[2][3]);
    mma_bf16(d[2][0], d[2][1], d[2][2], d[2][3], X01[0], X01[1], X01[2], X01[3],
             X11[0], X11[2], d[2][0], d[2][1], d[2][2], d[2][3]);
    mma_bf16(d[3][0], d[3][1], d[3][2], d[3][3], X10[0], X10[1], X10[2], X10[3],
             X10[0], X10[2], d[3][0], d[3][1], d[3][2], d[3][3]);
    mma_bf16(d[3][0], d[3][1], d[3][2], d[3][3], X11[0], X11[1], X11[2], X11[3],
             X11[0], X11[2], d[3][0], d[3][1], d[3][2], d[3][3]);
}

__global__ __launch_bounds__(256)
void w2dm_all(const float* __restrict__ Wt,
              const float* __restrict__ Wc,
              const int*   __restrict__ tidx,
              const int*   __restrict__ cidx,
              const int*   __restrict__ nidx,
              int kneg, int B, int vocab, float* __restrict__ out)
{
    __shared__ __align__(16) uint16_t s_rows[8][1024];     // 32x32 bf16 tiles
    __shared__ __align__(16) float    s_cp[8][DEPTH][400]; // fp32 staging
    __shared__ __align__(16) uint32_t s_g[8][TSTRIDE];
    __shared__ int s_wi[8][12];
    __shared__ unsigned s_last, s_lno;

    const int w    = threadIdx.x >> 5;
    const int lane = threadIdx.x & 31;

    // race-free launch identity: launches serialize, so ticket/grid == launch no.
    if (threadIdx.x == 0) s_lno = atomicAdd(&g_launch, 1u) / gridDim.x;
    __syncthreads();
    const unsigned Lno   = s_lno;
    const unsigned epoch = Lno + 1u;
    const int      par   = (int)(Lno & 1u);

    ull pol;
    asm("createpolicy.fractional.L2::evict_first.b64 %0, 1.0;" : "=l"(pol));

    // ── Phase 0: epoch mark + warp-aggregated dense-list append ──
    if (blockIdx.x == 0 && threadIdx.x == 0) g_cnt2[par ^ 1] = 0u;   // for NEXT launch
    {
        const int total = B * (1 + kneg);
        const int gstride = gridDim.x * 256;
        for (int t = blockIdx.x * 256 + threadIdx.x; ; t += gstride) {
            if (t - lane >= total) break;               // warp-uniform exit
            bool valid = (t < total);
            int v = 0;
            bool neww = false;
            if (valid) {
                v = (t < B) ? cidx[t] : nidx[t - B];
                neww = (atomicExch(&g_flagse[v], epoch) != epoch);
            }
            unsigned m = __ballot_sync(0xffffffffu, neww);
            if (m) {
                int leader = __ffs(m) - 1;
                int basei = 0;
                if (lane == leader) basei = (int)atomicAdd(&g_cnt2[par], (unsigned)__popc(m));
                basei = __shfl_sync(0xffffffffu, basei, leader);
                if (neww) {
                    int pos = basei + __popc(m & ((1u << lane) - 1u));
                    if (pos < VOCAB_MAX) g_list[pos] = v;
                }
            }
        }
    }
    grid_barrier();

    // ── Phase A: pipelined Gram features over the dense list ──
    zero_tile(s_rows[w], lane);
    __syncwarp();
    {
        int n = (int)*(volatile unsigned*)&g_cnt2[par];
        if (n > VOCAB_MAX) n = VOCAB_MAX;
        const int stride = gridDim.x * 8;
        const int base = blockIdx.x * 8 + w;
        const uint32_t cpb = smem_u32(&s_cp[w][0][0]);

        #pragma unroll
        for (int d = 0; d < DEPTH; d++) {               // prologue: fill pipeline
            int idx = base + d * stride;
            if (idx < n)
                cp_word(cpb + (uint32_t)d * 1600u, Wc + (size_t)g_list[idx] * 400, lane, pol);
            asm volatile("cp.async.commit_group;" ::: "memory");
        }

        int bufi = 0;
        for (int i = base; i < n; i += stride) {
            asm volatile("cp.async.wait_group %0;" :: "n"(DEPTH - 1) : "memory");
            const int word = g_list[i];
            conv_word(s_rows[w], s_cp[w][bufi], lane);
            __syncwarp();

            const int idx2 = i + DEPTH * stride;        // refill reclaimed buffer
            if (idx2 < n)
                cp_word(cpb + (uint32_t)bufi * 1600u, Wc + (size_t)g_list[idx2] * 400, lane, pol);
            asm volatile("cp.async.commit_group;" ::: "memory");

            float d[4][4];
            gram_hmma(smem_u32(s_rows[w]), lane, d);

            uint32_t* outp = g_hfeat + (size_t)word * TSTRIDE;
            const int lr = lane >> 2, lc = lane & 3;
            #pragma unroll
            for (int t = 0; t < 4; t++) {
                const int i0 = TILE_M0_[t] + lr;
                const int p  = (TILE_N0_[t] >> 1) + lc;
                const int i1 = i0 + 8;
                if (p < 10) {
                    if (i0 < 20 && p >= (i0 >> 1))
                        outp[trow(i0) - (i0 >> 1) + p] = bf2(d[t][1], d[t][0]);
                    if (i1 < 20 && p >= (i1 >> 1))
                        outp[trow(i1) - (i1 >> 1) + p] = bf2(d[t][3], d[t][2]);
                }
            }
            __syncwarp();

            bufi = (bufi + 1 == DEPTH) ? 0 : bufi + 1;
        }
    }
    grid_barrier();

    // ── Phase B: per-sample loss ──
    {
        const int stride = gridDim.x * 8;
        for (int b = blockIdx.x * 8 + w; b < B; b += stride) {
            if (lane < 12) {
                int v;
                if (lane == 0)      v = tidx[b];
                else if (lane == 1) v = cidx[b];
                else                v = nidx[b * kneg + (lane - 2)];
                s_wi[w][lane] = v;
            }
            __syncwarp();

            float4 tv[4];
            ld_word(tv, Wt + (size_t)s_wi[w][0] * 400, lane);
            sts_word(s_rows[w], tv, lane);
            __syncwarp();

            float d[4][4];
            gram_hmma(smem_u32(s_rows[w]), lane, d);

            const int lr = lane >> 2, lc = lane & 3;
            #pragma unroll
            for (int t = 0; t < 4; t++) {
                const int p = (TILE_N0_[t] >> 1) + lc;
                if (p < 10) {
                    #pragma unroll
                    for (int h = 0; h < 2; h++) {
                        const int i  = TILE_M0_[t] + lr + 8 * h;
                        const int qi = i >> 1;
                        if (i < 20 && p >= qi) {
                            uint32_t pair = bf2(d[t][2 * h + 1], d[t][2 * h]);
                            uint32_t wsel = (p > qi) ? 0x40004000u
                                          : ((i & 1) == 0 ? 0x40003F80u : 0x3F800000u);
                            s_g[w][trow(i) - qi + p] = hmul2(pair, wsel);
                        }
                    }
                }
            }
            __syncwarp();

            uint32_t pacc[NMATS];
            {
                const uint32_t g0 = s_g[w][lane];
                const uint32_t g1 = s_g[w][lane + 32];
                const uint32_t g2 = s_g[w][lane + 64];
                const uint32_t g3 = (lane + 96 < TPAIRS) ? s_g[w][lane + 96] : 0u;
                #pragma unroll
                for (int r = 0; r < NMATS; r++) {
                    const uint32_t* hp = g_hfeat + (size_t)s_wi[w][1 + r] * TSTRIDE;
                    uint32_t v0 = hp[lane];
                    uint32_t v1 = hp[lane + 32];
                    uint32_t v2 = hp[lane + 64];
                    uint32_t v3 = (lane + 96 < TPAIRS) ? hp[lane + 96] : 0u;
                    uint32_t p = 0;
                    p = hfma2(v0, g0, p);
                    p = hfma2(v1, g1, p);
                    p = hfma2(v2, g2, p);
                    p = hfma2(v3, g3, p);
                    pacc[r] = p;
                }
            }

            float prod = 1.0f;
            #pragma unroll
            for (int r = 0; r < NMATS; r++) {
                uint32_t p = pacc[r];
                #pragma unroll
                for (int dd = 16; dd; dd >>= 1)
                    p = hadd2(p, __shfl_xor_sync(0xffffffffu, p, dd));
                uint32_t tsum = hadd2(p, prmt(p, p, 0x1032u));
                float sim = __uint_as_float(tsum << 16);
                float y = (r == 0) ? -sim : sim;
                prod *= 1.0f + __expf(y);
            }
            if (lane == 0) g_partials[b] = __logf(prod);
            __syncwarp();
        }
    }
    __syncthreads();

    if (threadIdx.x == 0) {
        __threadfence();
        unsigned old = atomicAdd(&g_ctr, 1u);
        s_last = (old % (unsigned)gridDim.x == (unsigned)gridDim.x - 1u) ? 1u : 0u;
    }
    __syncthreads();

    if (s_last) {
        __shared__ float s_red[256];
        const int t = threadIdx.x;
        float acc = 0.0f;
        const int n4 = B >> 2;
        const float4* p = (const float4*)g_partials;
        for (int i = t; i < n4; i += 256) {
            float4 v = p[i];
            acc += (v.x + v.y) + (v.z + v.w);
        }
        s_red[t] = acc;
        __syncthreads();
        #pragma unroll
        for (int ww = 128; ww > 0; ww >>= 1) {
            if (t < ww) s_red[t] += s_red[t + ww];
            __syncthreads();
        }
        if (t == 0) out[0] = s_red[0] / (float)B;
    }
}

extern "C" void kernel_launch(void* const* d_in, const int* in_sizes, int n_in,
                              void* d_out, int out_size)
{
    const float* Wt   = (const float*)d_in[0];
    const float* Wc   = (const float*)d_in[1];
    const int*   tidx = (const int*)d_in[2];
    const int*   cidx = (const int*)d_in[3];
    const int*   nidx = (const int*)d_in[4];

    int vocab = in_sizes[1] / 400;
    int B = in_sizes[2];
    if (B > BMAX) B = BMAX;
    int kneg = in_sizes[4] / (B > 0 ? B : 1);

    int dev = 0;
    cudaGetDevice(&dev);
    int nsm = 0;
    cudaDeviceGetAttribute(&nsm, cudaDevAttrMultiProcessorCount, dev);
    if (nsm <= 0) nsm = 148;
    int maxb = 0;
    cudaOccupancyMaxActiveBlocksPerMultiprocessor(&maxb, w2dm_all, 256, 0);
    if (maxb < 1) maxb = 1;
    int grid = nsm * maxb;
    if (grid > 2048) grid = 2048;

    w2dm_all<<<grid, 256>>>(Wt, Wc, tidx, cidx, nidx, kneg, B, vocab, (float*)d_out);
}

// round 17
// speedup vs baseline: 1.0294x; 1.0294x over previous
#include <cuda_runtime.h>
#include <cstdint>

// Word2DM, fused persistent kernel, software-pipelined Phase A (cp.async depth 2):
// Phase 0 : epoch-stamped mark + warp-aggregated dense-list append (no scan).
// Phase A : per-warp HMMA Gram over dense list; 2-deep cp.async pipeline.
// Phase B : per-sample target Gram + 11 batched triangle dots, product-form softplus;
//           last-arriving block does the fixed-order mean.
// R17: DEPTH=2 + __launch_bounds__(256,4) -> 4 blocks/SM (occupancy restored).

#define NDIM      20
#define NMATS     11
#define BMAX      32768
#define VOCAB_MAX 100000
#define TPAIRS    110
#define TSTRIDE   112
#define DEPTH     2

__device__ float    g_partials[BMAX];
__device__ uint32_t g_hfeat[(size_t)VOCAB_MAX * TSTRIDE];   // 44.8 MB
__device__ unsigned g_flagse[VOCAB_MAX];                    // epoch stamps
__device__ int      g_list[VOCAB_MAX];
__device__ unsigned g_cnt2[2];     // parity ping-pong append counters
__device__ unsigned g_launch;      // launch ticket counter (monotonic)
__device__ unsigned g_bar;         // grid-barrier epochs (monotonic)
__device__ unsigned g_ctr;         // last-block-reduce counter (modulo pattern)

typedef unsigned long long ull;

static __device__ __forceinline__ uint32_t hfma2(uint32_t a, uint32_t b, uint32_t c) {
    uint32_t d;
    asm("fma.rn.bf16x2 %0, %1, %2, %3;" : "=r"(d) : "r"(a), "r"(b), "r"(c));
    return d;
}
static __device__ __forceinline__ uint32_t hadd2(uint32_t a, uint32_t b) {
    uint32_t d;
    asm("add.bf16x2 %0, %1, %2;" : "=r"(d) : "r"(a), "r"(b));
    return d;
}
static __device__ __forceinline__ uint32_t hmul2(uint32_t a, uint32_t b) {
    uint32_t d;
    asm("mul.bf16x2 %0, %1, %2;" : "=r"(d) : "r"(a), "r"(b));
    return d;
}
static __device__ __forceinline__ uint32_t prmt(uint32_t a, uint32_t b, uint32_t sel) {
    uint32_t d;
    asm("prmt.b32 %0, %1, %2, %3;" : "=r"(d) : "r"(a), "r"(b), "r"(sel));
    return d;
}
static __device__ __forceinline__ ull packu2(uint32_t lo, uint32_t hi) {
    ull r;
    asm("mov.b64 %0, {%1, %2};" : "=l"(r) : "r"(lo), "r"(hi));
    return r;
}
static __device__ __forceinline__ uint32_t bf2(float hi, float lo) {
    uint32_t r;
    asm("cvt.rn.bf16x2.f32 %0, %1, %2;" : "=r"(r) : "f"(hi), "f"(lo));
    return r;
}
static __device__ __forceinline__ uint32_t smem_u32(const void* p) {
    uint32_t a;
    asm("{ .reg .u64 t; cvta.to.shared.u64 t, %1; cvt.u32.u64 %0, t; }" : "=r"(a) : "l"(p));
    return a;
}
static __device__ __forceinline__ void ldsm_x4(uint32_t& r0, uint32_t& r1,
                                               uint32_t& r2, uint32_t& r3, uint32_t addr) {
    asm volatile("ldmatrix.sync.aligned.m8n8.x4.shared.b16 {%0,%1,%2,%3}, [%4];"
                 : "=r"(r0), "=r"(r1), "=r"(r2), "=r"(r3) : "r"(addr));
}
static __device__ __forceinline__ void mma_bf16(float& d0, float& d1, float& d2, float& d3,
                                                uint32_t a0, uint32_t a1, uint32_t a2, uint32_t a3,
                                                uint32_t b0, uint32_t b1,
                                                float c0, float c1, float c2, float c3) {
    asm volatile("mma.sync.aligned.m16n8k16.row.col.f32.bf16.bf16.f32 "
                 "{%0,%1,%2,%3}, {%4,%5,%6,%7}, {%8,%9}, {%10,%11,%12,%13};"
                 : "=f"(d0), "=f"(d1), "=f"(d2), "=f"(d3)
                 : "r"(a0), "r"(a1), "r"(a2), "r"(a3), "r"(b0), "r"(b1),
                   "f"(c0), "f"(c1), "f"(c2), "f"(c3));
}

static __device__ __forceinline__ void grid_barrier() {
    __syncthreads();
    if (threadIdx.x == 0) {
        __threadfence();
        unsigned o = atomicAdd(&g_bar, 1u);
        unsigned target = (o / gridDim.x + 1u) * gridDim.x;
        while ((int)(*(volatile unsigned*)&g_bar - target) < 0) { }
        __threadfence();
    }
    __syncthreads();
}

static __device__ __forceinline__ int trow(int i) {
    int t = i >> 1;
    return (i & 1) ? (20 * t + 10 - t * t) : (t * (21 - t));
}

static __device__ __forceinline__ void zero_tile(uint16_t* dst16, int lane) {
    uint4 z = make_uint4(0, 0, 0, 0);
    #pragma unroll
    for (int k = 0; k < 4; k++)
        *(uint4*)(dst16 + (lane + 32 * k) * 8) = z;
}

// one word's rows (400 f32 = 100x16B) via cp.async.cg, evict-first L2 policy
static __device__ __forceinline__ void cp_word(uint32_t sdst, const float* __restrict__ src,
                                               int lane, ull pol)
{
    #pragma unroll
    for (int k = 0; k < 4; k++) {
        int f = lane + 32 * k;
        if (f < 100)
            asm volatile("cp.async.cg.shared.global.L2::cache_hint [%0], [%1], 16, %2;"
                         :: "r"(sdst + (uint32_t)f * 16), "l"(src + f * 4), "l"(pol) : "memory");
    }
}
// convert fp32 staging buffer -> bf16 tile (64B row stride; pads untouched)
static __device__ __forceinline__ void conv_word(uint16_t* __restrict__ dst16,
                                                 const float* __restrict__ buf, int lane)
{
    const float4* s = (const float4*)buf;
    #pragma unroll
    for (int k = 0; k < 4; k++) {
        int f = lane + 32 * k;
        if (f < 100) {
            float4 v = s[f];
            int row = f / 5, q = f % 5;
            *(ull*)(dst16 + row * 32 + q * 4) = packu2(bf2(v.y, v.x), bf2(v.w, v.z));
        }
    }
}
static __device__ __forceinline__ void ld_word(float4* v, const float* __restrict__ src, int lane) {
    const float4* s = (const float4*)src;
    #pragma unroll
    for (int k = 0; k < 4; k++) {
        int f = lane + 32 * k;
        if (f < 100) v[k] = __ldcs(s + f);
    }
}
static __device__ __forceinline__ void sts_word(uint16_t* __restrict__ dst16,
                                                const float4* v, int lane) {
    #pragma unroll
    for (int k = 0; k < 4; k++) {
        int f = lane + 32 * k;
        if (f < 100) {
            int row = f / 5, q = f % 5;
            *(ull*)(dst16 + row * 32 + q * 4) =
                packu2(bf2(v[k].y, v[k].x), bf2(v[k].w, v[k].z));
        }
    }
}

__device__ __constant__ const int TILE_M0_[4] = {0, 0, 0, 16};
__device__ __constant__ const int TILE_N0_[4] = {0, 8, 16, 16};

static __device__ __forceinline__ void gram_hmma(uint32_t sb, int lane, float d[4][4]) {
    const int r = lane & 7, g = lane >> 3;
    uint32_t adr = sb + (uint32_t)((r + ((g & 1) ? 8 : 0)) * 64 + ((g >> 1) ? 16 : 0));
    uint32_t X00[4], X01[4], X10[4], X11[4];
    ldsm_x4(X00[0], X00[1], X00[2], X00[3], adr);
    ldsm_x4(X01[0], X01[1], X01[2], X01[3], adr + 32);
    ldsm_x4(X10[0], X10[1], X10[2], X10[3], adr + 1024);
    ldsm_x4(X11[0], X11[1], X11[2], X11[3], adr + 1024 + 32);

    #pragma unroll
    for (int t = 0; t < 4; t++) d[t][0] = d[t][1] = d[t][2] = d[t][3] = 0.0f;

    mma_bf16(d[0][0], d[0][1], d[0][2], d[0][3], X00[0], X00[1], X00[2], X00[3],
             X00[0], X00[2], d[0][0], d[0][1], d[0][2], d[0][3]);
    mma_bf16(d[0][0], d[0][1], d[0][2], d[0][3], X01[0], X01[1], X01[2], X01[3],
             X01[0], X01[2], d[0][0], d[0][1], d[0][2], d[0][3]);
    mma_bf16(d[1][0], d[1][1], d[1][2], d[1][3], X00[0], X00[1], X00[2], X00[3],
             X00[1], X00[3], d[1][0], d[1][1], d[1][2], d[1][3]);
    mma_bf16(d[1][0], d[1][1], d[1][2], d[1][3], X01[0], X01[1], X01[2], X01[3],
             X01[1], X01[3], d[1][0], d[1][1], d[1][2], d[1][3]);
    mma_bf16(d[2][0], d[2][1], d[2][2], d[2][3], X00[0], X00[1], X00[2], X00[3],
             X10[0], X10[2], d[2][0], d[2][1], d[2][2], d[2][3]);
    mma_bf16(d[2][0], d[2][1], d[2][2], d[2][3], X01[0], X01[1], X01[2], X01[3],
             X11[0], X11[2], d[2][0], d[2][1], d[2][2], d[2][3]);
    mma_bf16(d[3][0], d[3][1], d[3][2], d[3][3], X10[0], X10[1], X10[2], X10[3],
             X10[0], X10[2], d[3][0], d[3][1], d[3][2], d[3][3]);
    mma_bf16(d[3][0], d[3][1], d[3][2], d[3][3], X11[0], X11[1], X11[2], X11[3],
             X11[0], X11[2], d[3][0], d[3][1], d[3][2], d[3][3]);
}

__global__ __launch_bounds__(256, 4)
void w2dm_all(const float* __restrict__ Wt,
              const float* __restrict__ Wc,
              const int*   __restrict__ tidx,
              const int*   __restrict__ cidx,
              const int*   __restrict__ nidx,
              int kneg, int B, int vocab, float* __restrict__ out)
{
    __shared__ __align__(16) uint16_t s_rows[8][1024];     // 32x32 bf16 tiles, 16 KB
    __shared__ __align__(16) float    s_cp[8][DEPTH][400]; // fp32 staging, 25.6 KB
    __shared__ __align__(16) uint32_t s_g[8][TSTRIDE];
    __shared__ int s_wi[8][12];
    __shared__ unsigned s_last, s_lno;

    const int w    = threadIdx.x >> 5;
    const int lane = threadIdx.x & 31;

    // race-free launch identity: launches serialize, so ticket/grid == launch no.
    if (threadIdx.x == 0) s_lno = atomicAdd(&g_launch, 1u) / gridDim.x;
    __syncthreads();
    const unsigned Lno   = s_lno;
    const unsigned epoch = Lno + 1u;
    const int      par   = (int)(Lno & 1u);

    ull pol;
    asm("createpolicy.fractional.L2::evict_first.b64 %0, 1.0;" : "=l"(pol));

    // ── Phase 0: epoch mark + warp-aggregated dense-list append ──
    if (blockIdx.x == 0 && threadIdx.x == 0) g_cnt2[par ^ 1] = 0u;   // for NEXT launch
    {
        const int total = B * (1 + kneg);
        const int gstride = gridDim.x * 256;
        for (int t = blockIdx.x * 256 + threadIdx.x; ; t += gstride) {
            if (t - lane >= total) break;               // warp-uniform exit
            bool valid = (t < total);
            int v = 0;
            bool neww = false;
            if (valid) {
                v = (t < B) ? cidx[t] : nidx[t - B];
                neww = (atomicExch(&g_flagse[v], epoch) != epoch);
            }
            unsigned m = __ballot_sync(0xffffffffu, neww);
            if (m) {
                int leader = __ffs(m) - 1;
                int basei = 0;
                if (lane == leader) basei = (int)atomicAdd(&g_cnt2[par], (unsigned)__popc(m));
                basei = __shfl_sync(0xffffffffu, basei, leader);
                if (neww) {
                    int pos = basei + __popc(m & ((1u << lane) - 1u));
                    if (pos < VOCAB_MAX) g_list[pos] = v;
                }
            }
        }
    }
    grid_barrier();

    // ── Phase A: pipelined Gram features over the dense list ──
    zero_tile(s_rows[w], lane);
    __syncwarp();
    {
        int n = (int)*(volatile unsigned*)&g_cnt2[par];
        if (n > VOCAB_MAX) n = VOCAB_MAX;
        const int stride = gridDim.x * 8;
        const int base = blockIdx.x * 8 + w;
        const uint32_t cpb = smem_u32(&s_cp[w][0][0]);

        #pragma unroll
        for (int d = 0; d < DEPTH; d++) {               // prologue: fill pipeline
            int idx = base + d * stride;
            if (idx < n)
                cp_word(cpb + (uint32_t)d * 1600u, Wc + (size_t)g_list[idx] * 400, lane, pol);
            asm volatile("cp.async.commit_group;" ::: "memory");
        }

        int bufi = 0;
        for (int i = base; i < n; i += stride) {
            asm volatile("cp.async.wait_group %0;" :: "n"(DEPTH - 1) : "memory");
            const int word = g_list[i];
            conv_word(s_rows[w], s_cp[w][bufi], lane);
            __syncwarp();

            const int idx2 = i + DEPTH * stride;        // refill reclaimed buffer
            if (idx2 < n)
                cp_word(cpb + (uint32_t)bufi * 1600u, Wc + (size_t)g_list[idx2] * 400, lane, pol);
            asm volatile("cp.async.commit_group;" ::: "memory");

            float d[4][4];
            gram_hmma(smem_u32(s_rows[w]), lane, d);

            uint32_t* outp = g_hfeat + (size_t)word * TSTRIDE;
            const int lr = lane >> 2, lc = lane & 3;
            #pragma unroll
            for (int t = 0; t < 4; t++) {
                const int i0 = TILE_M0_[t] + lr;
                const int p  = (TILE_N0_[t] >> 1) + lc;
                const int i1 = i0 + 8;
                if (p < 10) {
                    if (i0 < 20 && p >= (i0 >> 1))
                        outp[trow(i0) - (i0 >> 1) + p] = bf2(d[t][1], d[t][0]);
                    if (i1 < 20 && p >= (i1 >> 1))
                        outp[trow(i1) - (i1 >> 1) + p] = bf2(d[t][3], d[t][2]);
                }
            }
            __syncwarp();

            bufi ^= (DEPTH - 1);                        // DEPTH=2 toggle
        }
    }
    grid_barrier();

    // ── Phase B: per-sample loss ──
    {
        const int stride = gridDim.x * 8;
        for (int b = blockIdx.x * 8 + w; b < B; b += stride) {
            if (lane < 12) {
                int v;
                if (lane == 0)      v = tidx[b];
                else if (lane == 1) v = cidx[b];
                else                v = nidx[b * kneg + (lane - 2)];
                s_wi[w][lane] = v;
            }
            __syncwarp();

            float4 tv[4];
            ld_word(tv, Wt + (size_t)s_wi[w][0] * 400, lane);
            sts_word(s_rows[w], tv, lane);
            __syncwarp();

            float d[4][4];
            gram_hmma(smem_u32(s_rows[w]), lane, d);

            const int lr = lane >> 2, lc = lane & 3;
            #pragma unroll
            for (int t = 0; t < 4; t++) {
                const int p = (TILE_N0_[t] >> 1) + lc;
                if (p < 10) {
                    #pragma unroll
                    for (int h = 0; h < 2; h++) {
                        const int i  = TILE_M0_[t] + lr + 8 * h;
                        const int qi = i >> 1;
                        if (i < 20 && p >= qi) {
                            uint32_t pair = bf2(d[t][2 * h + 1], d[t][2 * h]);
                            uint32_t wsel = (p > qi) ? 0x40004000u
                                          : ((i & 1) == 0 ? 0x40003F80u : 0x3F800000u);
                            s_g[w][trow(i) - qi + p] = hmul2(pair, wsel);
                        }
                    }
                }
            }
            __syncwarp();

            uint32_t pacc[NMATS];
            {
                const uint32_t g0 = s_g[w][lane];
                const uint32_t g1 = s_g[w][lane + 32];
                const uint32_t g2 = s_g[w][lane + 64];
                const uint32_t g3 = (lane + 96 < TPAIRS) ? s_g[w][lane + 96] : 0u;
                #pragma unroll
                for (int r = 0; r < NMATS; r++) {
                    const uint32_t* hp = g_hfeat + (size_t)s_wi[w][1 + r] * TSTRIDE;
                    uint32_t v0 = hp[lane];
                    uint32_t v1 = hp[lane + 32];
                    uint32_t v2 = hp[lane + 64];
                    uint32_t v3 = (lane + 96 < TPAIRS) ? hp[lane + 96] : 0u;
                    uint32_t p = 0;
                    p = hfma2(v0, g0, p);
                    p = hfma2(v1, g1, p);
                    p = hfma2(v2, g2, p);
                    p = hfma2(v3, g3, p);
                    pacc[r] = p;
                }
            }

            float prod = 1.0f;
            #pragma unroll
            for (int r = 0; r < NMATS; r++) {
                uint32_t p = pacc[r];
                #pragma unroll
                for (int dd = 16; dd; dd >>= 1)
                    p = hadd2(p, __shfl_xor_sync(0xffffffffu, p, dd));
                uint32_t tsum = hadd2(p, prmt(p, p, 0x1032u));
                float sim = __uint_as_float(tsum << 16);
                float y = (r == 0) ? -sim : sim;
                prod *= 1.0f + __expf(y);
            }
            if (lane == 0) g_partials[b] = __logf(prod);
            __syncwarp();
        }
    }
    __syncthreads();

    if (threadIdx.x == 0) {
        __threadfence();
        unsigned old = atomicAdd(&g_ctr, 1u);
        s_last = (old % (unsigned)gridDim.x == (unsigned)gridDim.x - 1u) ? 1u : 0u;
    }
    __syncthreads();

    if (s_last) {
        __shared__ float s_red[256];
        const int t = threadIdx.x;
        float acc = 0.0f;
        const int n4 = B >> 2;
        const float4* p = (const float4*)g_partials;
        for (int i = t; i < n4; i += 256) {
            float4 v = p[i];
            acc += (v.x + v.y) + (v.z + v.w);
        }
        s_red[t] = acc;
        __syncthreads();
        #pragma unroll
        for (int ww = 128; ww > 0; ww >>= 1) {
            if (t < ww) s_red[t] += s_red[t + ww];
            __syncthreads();
        }
        if (t == 0) out[0] = s_red[0] / (float)B;
    }
}

extern "C" void kernel_launch(void* const* d_in, const int* in_sizes, int n_in,
                              void* d_out, int out_size)
{
    const float* Wt   = (const float*)d_in[0];
    const float* Wc   = (const float*)d_in[1];
    const int*   tidx = (const int*)d_in[2];
    const int*   cidx = (const int*)d_in[3];
    const int*   nidx = (const int*)d_in[4];

    int vocab = in_sizes[1] / 400;
    int B = in_sizes[2];
    if (B > BMAX) B = BMAX;
    int kneg = in_sizes[4] / (B > 0 ? B : 1);

    int dev = 0;
    cudaGetDevice(&dev);
    int nsm = 0;
    cudaDeviceGetAttribute(&nsm, cudaDevAttrMultiProcessorCount, dev);
    if (nsm <= 0) nsm = 148;
    int maxb = 0;
    cudaOccupancyMaxActiveBlocksPerMultiprocessor(&maxb, w2dm_all, 256, 0);
    if (maxb < 1) maxb = 1;
    int grid = nsm * maxb;
    if (grid > 2048) grid = 2048;

    w2dm_all<<<grid, 256>>>(Wt, Wc, tidx, cidx, nidx, kneg, B, vocab, (float*)d_out);
}